// round 2
// baseline (speedup 1.0000x reference)
#include <cuda_runtime.h>
#include <cuda_fp16.h>

#define NB 64
#define NT 512
#define DIN 512
#define HID 1024
#define NCTA 128
#define NTHR 256

#define APITCH 72              // halves per A row (64 + 8 pad)
#define ABUFH (64*APITCH)

#define KP0 1544               // weight pitch halves (1536+8)
#define KP1 2056               // (2048+8)

#define WS_OFF   0
#define AB_OFF   131584
#define PACC_OFF 150016
#define PACC_PITCH 34
#define CS_OFF   184832
#define BS_OFF   186880
#define SMEM_BYTES 187008

__device__ __align__(256) __half g_Xh[NT*NB*DIN];   // [t][b][d] fp16 input
__device__ __align__(256) __half g_X1[NT*NB*HID];   // layer0 outputs = layer1 inputs
__device__ __align__(256) __half g_H[2][NB*HID];    // ping-pong hidden state
__device__ unsigned g_bar;

__device__ __forceinline__ unsigned sptr(const void* p) {
  return (unsigned)__cvta_generic_to_shared(p);
}
__device__ __forceinline__ void cp16(unsigned d, const void* s) {
  asm volatile("cp.async.cg.shared.global [%0], [%1], 16;" :: "r"(d), "l"(s));
}
__device__ __forceinline__ void cpcommit() { asm volatile("cp.async.commit_group;"); }
__device__ __forceinline__ void cpwait1()  { asm volatile("cp.async.wait_group 1;"); }
__device__ __forceinline__ void cpwait0()  { asm volatile("cp.async.wait_group 0;"); }

__device__ __forceinline__ void gridbar() {
  __syncthreads();
  if (threadIdx.x == 0) {
    unsigned t, cur;
    asm volatile("atom.add.release.gpu.u32 %0, [%1], 1;" : "=r"(t) : "l"(&g_bar) : "memory");
    unsigned target = (t & ~(unsigned)(NCTA-1)) + NCTA;
    do {
      asm volatile("ld.acquire.gpu.u32 %0, [%1];" : "=r"(cur) : "l"(&g_bar) : "memory");
    } while ((int)(cur - target) < 0);
  }
  __syncthreads();
}

__device__ __forceinline__ void hmma(float* d, const unsigned* a, const unsigned* b) {
  asm volatile("mma.sync.aligned.m16n8k16.row.col.f32.f16.f16.f32 "
    "{%0,%1,%2,%3}, {%4,%5,%6,%7}, {%8,%9}, {%0,%1,%2,%3};"
    : "+f"(d[0]), "+f"(d[1]), "+f"(d[2]), "+f"(d[3])
    : "r"(a[0]), "r"(a[1]), "r"(a[2]), "r"(a[3]), "r"(b[0]), "r"(b[1]));
}

__device__ __forceinline__ float sigf(float x)     { return 1.f/(1.f+__expf(-x)); }
__device__ __forceinline__ float tanhfast(float x) { return 1.f - 2.f/(1.f+__expf(2.f*x)); }

template<int LAYER>
__device__ void load_layer(char* smem, const float* W, const float* U,
                           const float* bias, const float* h0, const float* c0)
{
  constexpr int D  = (LAYER==0) ? DIN : HID;
  constexpr int K  = D + HID;
  constexpr int KP = (LAYER==0) ? KP0 : KP1;
  __half* ws = (__half*)(smem + WS_OFF);
  float* cs  = (float*)(smem + CS_OFF);
  float* bsm = (float*)(smem + BS_OFF);
  const int tid = threadIdx.x, cta = blockIdx.x;

  for (int idx = tid; idx < 32*K; idx += NTHR) {
    int n8   = idx & 7;
    int rest = idx >> 3;
    int k    = rest % K;
    int gate = rest / K;
    int colg = cta*8 + n8 + gate*HID;
    float v = (k < D) ? W[(size_t)k*4*HID + colg] : U[(size_t)(k-D)*4*HID + colg];
    ws[(gate*8 + n8)*KP + k] = __float2half_rn(v);
  }
  if (tid < 32) bsm[tid] = bias[cta*8 + (tid&7) + (tid>>3)*HID];
  #pragma unroll
  for (int e0 = 0; e0 < 2; ++e0) {
    int item = tid + e0*NTHR;            // 0..511 = (b, hc)
    int b = item>>3, hc = item&7, col = cta*8 + hc;
    cs[item] = c0[b*HID + col];
    g_H[0][b*HID + col] = __float2half_rn(h0[b*HID + col]);
  }
}

template<int LAYER>
__device__ void run_layer(char* smem, const __half* xseq, float* out, int out_size)
{
  constexpr int XP  = (LAYER==0) ? DIN : HID;   // x-part pitch
  constexpr int K   = XP + HID;
  constexpr int KP  = (LAYER==0) ? KP0 : KP1;
  constexpr int XCH = XP/64;
  constexpr int NCH = K/64;

  __half* ws   = (__half*)(smem + WS_OFF);
  __half* ab   = (__half*)(smem + AB_OFF);
  float* pacc  = (float*)(smem + PACC_OFF);
  float* cs    = (float*)(smem + CS_OFF);
  float* bsm   = (float*)(smem + BS_OFF);

  const int tid = threadIdx.x, cta = blockIdx.x;
  const int wid = tid>>5, lane = tid&31;
  const int mtg = wid&1, kg = wid>>1;          // 2 m-tile groups x 4 k-split groups
  const int r = lane>>2, cc = (lane&3)*2;

  for (int t = 0; t < NT; ++t) {
    const __half* xs = xseq + (size_t)t*NB*XP;
    const __half* hs = g_H[t&1];

    // prologue: stage chunk 0
    {
      unsigned dst = sptr(ab);
      #pragma unroll
      for (int e0 = 0; e0 < 2; ++e0) {
        int e = tid + e0*NTHR; int row = e>>3, seg = e&7;
        cp16(dst + row*(APITCH*2) + seg*16, xs + row*XP + seg*8);
      }
      cpcommit();
    }

    float acc[2][4][4];
    #pragma unroll
    for (int m = 0; m < 2; ++m)
      #pragma unroll
      for (int n = 0; n < 4; ++n) {
        float b0v = (kg==0) ? bsm[n*8+cc]   : 0.f;   // bias only in k-group 0
        float b1v = (kg==0) ? bsm[n*8+cc+1] : 0.f;
        acc[m][n][0]=b0v; acc[m][n][1]=b1v; acc[m][n][2]=b0v; acc[m][n][3]=b1v;
      }

    for (int ch = 0; ch < NCH; ++ch) {
      if (ch+1 < NCH) {
        unsigned dst = sptr(ab + ((ch+1)&1)*ABUFH);
        int c2 = ch+1;
        #pragma unroll
        for (int e0 = 0; e0 < 2; ++e0) {
          int e = tid + e0*NTHR; int row = e>>3, seg = e&7;
          const __half* src = (c2 < XCH) ? (xs + row*XP  + c2*64        + seg*8)
                                         : (hs + row*HID + (c2-XCH)*64 + seg*8);
          cp16(dst + row*(APITCH*2) + seg*16, src);
        }
        cpcommit();
        cpwait1();
      } else {
        cpwait0();
      }
      __syncthreads();

      const __half* A = ab + (ch&1)*ABUFH + kg*16;
      unsigned av[2][4], bv[4][2];
      #pragma unroll
      for (int m = 0; m < 2; ++m) {
        int row0 = (mtg*2+m)*16 + r;
        const __half* Ar = A + row0*APITCH + cc;
        av[m][0] = *(const unsigned*)(Ar);
        av[m][1] = *(const unsigned*)(Ar + 8*APITCH);
        av[m][2] = *(const unsigned*)(Ar + 8);
        av[m][3] = *(const unsigned*)(Ar + 8*APITCH + 8);
      }
      const int kb = ch*64 + kg*16 + cc;
      #pragma unroll
      for (int n = 0; n < 4; ++n) {
        const __half* Wr = ws + (n*8 + r)*KP + kb;
        bv[n][0] = *(const unsigned*)(Wr);
        bv[n][1] = *(const unsigned*)(Wr + 8);
      }
      #pragma unroll
      for (int m = 0; m < 2; ++m)
        #pragma unroll
        for (int n = 0; n < 4; ++n)
          hmma(acc[m][n], av[m], bv[n]);
      __syncthreads();
    }

    // write k-split partials
    #pragma unroll
    for (int m = 0; m < 2; ++m) {
      int row0 = (mtg*2+m)*16 + r;
      #pragma unroll
      for (int n = 0; n < 4; ++n) {
        int col = n*8 + cc;
        float* p = pacc + (kg*64 + row0)*PACC_PITCH + col;
        *(float2*)p                    = make_float2(acc[m][n][0], acc[m][n][1]);
        *(float2*)(p + 8*PACC_PITCH)   = make_float2(acc[m][n][2], acc[m][n][3]);
      }
    }
    __syncthreads();

    // reduce partials + LSTM cell update (512 items, 2 per thread)
    #pragma unroll
    for (int e0 = 0; e0 < 2; ++e0) {
      int item = tid + e0*NTHR;
      int b = item>>3, hc = item&7;
      float gi=0.f, gf=0.f, gg=0.f, go=0.f;
      #pragma unroll
      for (int q = 0; q < 4; ++q) {
        const float* p = pacc + (q*64 + b)*PACC_PITCH;
        gi += p[hc]; gf += p[8+hc]; gg += p[16+hc]; go += p[24+hc];
      }
      float cprev = cs[item];
      float cn = sigf(gf)*cprev + sigf(gi)*tanhfast(gg);
      float hn = sigf(go)*tanhfast(cn);
      cs[item] = cn;
      int col = cta*8 + hc;
      g_H[(t+1)&1][b*HID + col] = __float2half_rn(hn);
      if (LAYER == 0) {
        g_X1[((size_t)t*NB + b)*HID + col] = __float2half_rn(hn);
      } else {
        out[((size_t)b*NT + t)*HID + col] = hn;
        if (t == NT-1 && out_size >= NB*NT*HID + 2*NB*HID) {
          out[(size_t)NB*NT*HID + b*HID + col]            = hn;
          out[(size_t)NB*NT*HID + NB*HID + b*HID + col]   = cn;
        }
      }
    }
    gridbar();
  }
}

extern "C" __global__ void __launch_bounds__(NTHR, 1)
lstm_kernel(const float* x, const float* h0, const float* c0,
            const float* W0, const float* U0, const float* b0,
            const float* W1, const float* U1, const float* b1,
            float* out, int out_size)
{
  extern __shared__ char smem[];
  // init: transpose input to [t][b][d] fp16
  const size_t gtid = blockIdx.x*NTHR + threadIdx.x;
  for (size_t idx = gtid; idx < (size_t)NB*NT*DIN; idx += (size_t)NCTA*NTHR) {
    size_t d = idx & (DIN-1);
    size_t t = (idx >> 9) & (NT-1);
    size_t b = idx >> 18;
    g_Xh[((t*NB + b)<<9) + d] = __float2half_rn(x[idx]);
  }
  load_layer<0>(smem, W0, U0, b0, h0, c0);
  gridbar();
  run_layer<0>(smem, g_Xh, out, out_size);
  load_layer<1>(smem, W1, U1, b1, h0 + NB*HID, c0 + NB*HID);
  gridbar();
  run_layer<1>(smem, g_X1, out, out_size);
}

extern "C" void kernel_launch(void* const* d_in, const int* in_sizes, int n_in,
                              void* d_out, int out_size) {
  cudaFuncSetAttribute(lstm_kernel, cudaFuncAttributeMaxDynamicSharedMemorySize, SMEM_BYTES);
  lstm_kernel<<<NCTA, NTHR, SMEM_BYTES>>>(
      (const float*)d_in[0], (const float*)d_in[1], (const float*)d_in[2],
      (const float*)d_in[3], (const float*)d_in[4], (const float*)d_in[5],
      (const float*)d_in[6], (const float*)d_in[7], (const float*)d_in[8],
      (float*)d_out, out_size);
}

// round 3
// speedup vs baseline: 1.2069x; 1.2069x over previous
#include <cuda_runtime.h>
#include <cuda_fp16.h>

#define NB 64
#define NT 512
#define DIN 512
#define HID 1024
#define NCTA 128
#define NTHR 256

#define KP0 1544               // weight pitch halves (1536+8)
#define KP1 2056               // (2048+8)

#define WS_OFF   0
#define PACC_OFF 131584
#define PACC_PITCH 34
#define CS_OFF   166400
#define BS_OFF   168448
#define SMEM_BYTES 168576

__device__ __align__(256) __half g_Xh[NT*NB*DIN];   // [t][b][d] fp16, k-permuted
__device__ __align__(256) __half g_X1[NT*NB*HID];   // layer0 outputs, k-permuted
__device__ __align__(256) __half g_H[2][NB*HID];    // ping-pong hidden, k-permuted
__device__ unsigned g_bar;

// within-16 k permutation: pos 4c..4c+3 hold k {2c,2c+1,2c+8,2c+9}
__device__ __forceinline__ int permk(int k) {
  return (k & ~15) | ((k & 6) << 1) | ((k & 8) >> 2) | (k & 1);
}

__device__ __forceinline__ void gridbar() {
  __syncthreads();
  if (threadIdx.x == 0) {
    unsigned t, cur;
    asm volatile("atom.add.release.gpu.u32 %0, [%1], 1;" : "=r"(t) : "l"(&g_bar) : "memory");
    unsigned target = (t & ~(unsigned)(NCTA-1)) + NCTA;
    do {
      asm volatile("ld.acquire.gpu.u32 %0, [%1];" : "=r"(cur) : "l"(&g_bar) : "memory");
    } while ((int)(cur - target) < 0);
  }
  __syncthreads();
}

__device__ __forceinline__ void hmma(float* d, const unsigned* a, const unsigned* b) {
  asm volatile("mma.sync.aligned.m16n8k16.row.col.f32.f16.f16.f32 "
    "{%0,%1,%2,%3}, {%4,%5,%6,%7}, {%8,%9}, {%0,%1,%2,%3};"
    : "+f"(d[0]), "+f"(d[1]), "+f"(d[2]), "+f"(d[3])
    : "r"(a[0]), "r"(a[1]), "r"(a[2]), "r"(a[3]), "r"(b[0]), "r"(b[1]));
}

__device__ __forceinline__ float sigf(float x)     { return 1.f/(1.f+__expf(-x)); }
__device__ __forceinline__ float tanhfast(float x) { return 1.f - 2.f/(1.f+__expf(2.f*x)); }

template<int LAYER>
__device__ void load_layer(char* smem, const float* W, const float* U,
                           const float* bias, const float* h0, const float* c0)
{
  constexpr int D  = (LAYER==0) ? DIN : HID;
  constexpr int K  = D + HID;
  constexpr int KP = (LAYER==0) ? KP0 : KP1;
  __half* ws = (__half*)(smem + WS_OFF);
  float* cs  = (float*)(smem + CS_OFF);
  float* bsm = (float*)(smem + BS_OFF);
  const int tid = threadIdx.x, cta = blockIdx.x;

  for (int idx = tid; idx < 32*K; idx += NTHR) {
    int n8   = idx & 7;
    int rest = idx >> 3;
    int k    = rest % K;
    int gate = rest / K;
    int colg = cta*8 + n8 + gate*HID;
    float v = (k < D) ? W[(size_t)k*4*HID + colg] : U[(size_t)(k-D)*4*HID + colg];
    ws[(gate*8 + n8)*KP + k] = __float2half_rn(v);
  }
  if (tid < 32) bsm[tid] = bias[cta*8 + (tid&7) + (tid>>3)*HID];
  #pragma unroll
  for (int e0 = 0; e0 < 2; ++e0) {
    int item = tid + e0*NTHR;            // 0..511 = (b, hc)
    int b = item>>3, hc = item&7, col = cta*8 + hc;
    cs[item] = c0[b*HID + col];
    g_H[0][b*HID + permk(col)] = __float2half_rn(h0[b*HID + col]);
  }
}

template<int LAYER>
__device__ void run_layer(char* smem, const __half* xseq, float* out, int out_size)
{
  constexpr int XP  = (LAYER==0) ? DIN : HID;   // x-part width
  constexpr int K   = XP + HID;
  constexpr int KP  = (LAYER==0) ? KP0 : KP1;
  constexpr int KQ  = K/4;                      // per k-group
  constexpr int NCH = KQ/16;                    // 24 or 32 (div by 4)

  __half* ws   = (__half*)(smem + WS_OFF);
  float* pacc  = (float*)(smem + PACC_OFF);
  float* cs    = (float*)(smem + CS_OFF);
  float* bsm   = (float*)(smem + BS_OFF);

  const int tid = threadIdx.x, cta = blockIdx.x;
  const int wid = tid>>5, lane = tid&31;
  const int mtg = wid&1, kg = wid>>1;           // 2 m-groups x 4 k-groups
  const int r = lane>>2, cq = lane&3;
  const int row00 = mtg*32 + r;                 // m-tile 0
  const int row01 = row00 + 16;                 // m-tile 1

  for (int t = 0; t < NT; ++t) {
    const __half* xs = xseq + (size_t)t*NB*XP;
    const __half* hs = g_H[t&1];

    float acc[2][4][4];
    #pragma unroll
    for (int m = 0; m < 2; ++m)
      #pragma unroll
      for (int n = 0; n < 4; ++n) {
        float b0v = (kg==0) ? bsm[n*8+2*cq]   : 0.f;
        float b1v = (kg==0) ? bsm[n*8+2*cq+1] : 0.f;
        acc[m][n][0]=b0v; acc[m][n][1]=b1v; acc[m][n][2]=b0v; acc[m][n][3]=b1v;
      }

    uint2 a[4][2][2];  // [slot][mtile][row r / row r+8]

#define LOADC(CH, S) do {                                                  \
    const int kb_ = kg*KQ + (CH)*16;                                       \
    const __half* pa_; int pit_;                                           \
    if (kb_ < XP) { pa_ = xs + kb_;        pit_ = XP;  }                   \
    else          { pa_ = hs + (kb_ - XP); pit_ = HID; }                   \
    const __half* p0_ = pa_ + row00*pit_ + 4*cq;                           \
    const __half* p1_ = pa_ + row01*pit_ + 4*cq;                           \
    a[S][0][0] = __ldcg((const uint2*)(p0_));                              \
    a[S][0][1] = __ldcg((const uint2*)(p0_ + 8*pit_));                     \
    a[S][1][0] = __ldcg((const uint2*)(p1_));                              \
    a[S][1][1] = __ldcg((const uint2*)(p1_ + 8*pit_));                     \
  } while(0)

    LOADC(0,0); LOADC(1,1); LOADC(2,2); LOADC(3,3);

    #pragma unroll 1
    for (int ch = 0; ch < NCH; ch += 4) {
      #pragma unroll
      for (int s = 0; s < 4; ++s) {
        const int cur = ch + s;
        uint2 av[2][2];
        av[0][0]=a[s][0][0]; av[0][1]=a[s][0][1];
        av[1][0]=a[s][1][0]; av[1][1]=a[s][1][1];
        if (cur + 4 < NCH) LOADC(cur+4, s);

        const int kb = kg*KQ + cur*16;
        unsigned bv0[4], bv1[4];
        #pragma unroll
        for (int n = 0; n < 4; ++n) {
          const __half* Wr = ws + (n*8 + r)*KP + kb + 2*cq;
          bv0[n] = *(const unsigned*)(Wr);
          bv1[n] = *(const unsigned*)(Wr + 8);
        }
        #pragma unroll
        for (int m = 0; m < 2; ++m) {
          unsigned aa[4] = {av[m][0].x, av[m][1].x, av[m][0].y, av[m][1].y};
          #pragma unroll
          for (int n = 0; n < 4; ++n) {
            unsigned bb[2] = {bv0[n], bv1[n]};
            hmma(acc[m][n], aa, bb);
          }
        }
      }
    }
#undef LOADC

    // write k-split partials
    #pragma unroll
    for (int m = 0; m < 2; ++m) {
      int row0 = (mtg*2+m)*16 + r;
      #pragma unroll
      for (int n = 0; n < 4; ++n) {
        int col = n*8 + 2*cq;
        float* p = pacc + (kg*64 + row0)*PACC_PITCH + col;
        *(float2*)p                    = make_float2(acc[m][n][0], acc[m][n][1]);
        *(float2*)(p + 8*PACC_PITCH)   = make_float2(acc[m][n][2], acc[m][n][3]);
      }
    }
    __syncthreads();

    // reduce partials + LSTM cell update (512 items, 2 per thread)
    #pragma unroll
    for (int e0 = 0; e0 < 2; ++e0) {
      int item = tid + e0*NTHR;
      int b = item>>3, hc = item&7;
      float gi=0.f, gf=0.f, gg=0.f, go=0.f;
      #pragma unroll
      for (int q = 0; q < 4; ++q) {
        const float* p = pacc + (q*64 + b)*PACC_PITCH;
        gi += p[hc]; gf += p[8+hc]; gg += p[16+hc]; go += p[24+hc];
      }
      float cprev = cs[item];
      float cn = sigf(gf)*cprev + sigf(gi)*tanhfast(gg);
      float hn = sigf(go)*tanhfast(cn);
      cs[item] = cn;
      int col = cta*8 + hc;
      __half hh = __float2half_rn(hn);
      g_H[(t+1)&1][b*HID + permk(col)] = hh;
      if (LAYER == 0) {
        g_X1[((size_t)t*NB + b)*HID + permk(col)] = hh;
      } else {
        out[((size_t)b*NT + t)*HID + col] = hn;
        if (t == NT-1 && out_size >= NB*NT*HID + 2*NB*HID) {
          out[(size_t)NB*NT*HID + b*HID + col]            = hn;
          out[(size_t)NB*NT*HID + NB*HID + b*HID + col]   = cn;
        }
      }
    }
    gridbar();
  }
}

extern "C" __global__ void __launch_bounds__(NTHR, 1)
lstm_kernel(const float* x, const float* h0, const float* c0,
            const float* W0, const float* U0, const float* b0,
            const float* W1, const float* U1, const float* b1,
            float* out, int out_size)
{
  extern __shared__ char smem[];
  // init: transpose input to [t][b][d] fp16, k-permuted within 16-groups
  const size_t gtid = blockIdx.x*NTHR + threadIdx.x;
  for (size_t idx = gtid; idx < (size_t)NB*NT*DIN; idx += (size_t)NCTA*NTHR) {
    int d = (int)(idx & (DIN-1));
    size_t t = (idx >> 9) & (NT-1);
    size_t b = idx >> 18;
    g_Xh[((t*NB + b)<<9) + permk(d)] = __float2half_rn(x[idx]);
  }
  load_layer<0>(smem, W0, U0, b0, h0, c0);
  gridbar();
  run_layer<0>(smem, g_Xh, out, out_size);
  load_layer<1>(smem, W1, U1, b1, h0 + NB*HID, c0 + NB*HID);
  gridbar();
  run_layer<1>(smem, g_X1, out, out_size);
}

extern "C" void kernel_launch(void* const* d_in, const int* in_sizes, int n_in,
                              void* d_out, int out_size) {
  cudaFuncSetAttribute(lstm_kernel, cudaFuncAttributeMaxDynamicSharedMemorySize, SMEM_BYTES);
  lstm_kernel<<<NCTA, NTHR, SMEM_BYTES>>>(
      (const float*)d_in[0], (const float*)d_in[1], (const float*)d_in[2],
      (const float*)d_in[3], (const float*)d_in[4], (const float*)d_in[5],
      (const float*)d_in[6], (const float*)d_in[7], (const float*)d_in[8],
      (float*)d_out, out_size);
}

// round 4
// speedup vs baseline: 1.5561x; 1.2894x over previous
#include <cuda_runtime.h>
#include <cuda_fp16.h>

#define NB 64
#define NT 512
#define DIN 512
#define HID 1024
#define NCTA 128
#define NTHR 256

// ---------------- global scratch ----------------
__device__ __align__(256) __half g_Xh[NT*NB*DIN];     // [t*64+b][512] fp16
__device__ __align__(256) __half g_X1[NT*NB*HID];     // layer0 outputs
__device__ __align__(256) float  g_GB[(size_t)NT*NB*4*HID]; // gate base (x@W+b), reused per layer
__device__ __align__(256) __half g_W0T[4*HID*DIN];    // [4096][512]  W0^T fp16
__device__ __align__(256) __half g_W1T[4*HID*HID];    // [4096][1024]
__device__ __align__(256) __half g_U0T[4*HID*HID];
__device__ __align__(256) __half g_U1T[4*HID*HID];
__device__ __align__(256) __half g_H[2][NB*HID];
__device__ unsigned g_bar;

// ---------------- helpers ----------------
__device__ __forceinline__ unsigned sptr(const void* p) {
  return (unsigned)__cvta_generic_to_shared(p);
}
__device__ __forceinline__ void cp16(unsigned d, const void* s) {
  asm volatile("cp.async.cg.shared.global [%0], [%1], 16;" :: "r"(d), "l"(s));
}
__device__ __forceinline__ void cpcommit() { asm volatile("cp.async.commit_group;"); }
__device__ __forceinline__ void cpwait0()  { asm volatile("cp.async.wait_group 0;"); }
__device__ __forceinline__ void cpwait1()  { asm volatile("cp.async.wait_group 1;"); }

__device__ __forceinline__ void ldsm4(unsigned* r, unsigned addr) {
  asm volatile("ldmatrix.sync.aligned.m8n8.x4.shared.b16 {%0,%1,%2,%3}, [%4];"
    : "=r"(r[0]), "=r"(r[1]), "=r"(r[2]), "=r"(r[3]) : "r"(addr));
}
__device__ __forceinline__ void hmma(float* d, const unsigned* a, const unsigned* b) {
  asm volatile("mma.sync.aligned.m16n8k16.row.col.f32.f16.f16.f32 "
    "{%0,%1,%2,%3}, {%4,%5,%6,%7}, {%8,%9}, {%0,%1,%2,%3};"
    : "+f"(d[0]), "+f"(d[1]), "+f"(d[2]), "+f"(d[3])
    : "r"(a[0]), "r"(a[1]), "r"(a[2]), "r"(a[3]), "r"(b[0]), "r"(b[1]));
}
__device__ __forceinline__ void gridbar() {
  __syncthreads();
  if (threadIdx.x == 0) {
    unsigned t, cur;
    asm volatile("atom.add.release.gpu.u32 %0, [%1], 1;" : "=r"(t) : "l"(&g_bar) : "memory");
    unsigned target = (t & ~(unsigned)(NCTA-1)) + NCTA;
    do {
      asm volatile("ld.acquire.gpu.u32 %0, [%1];" : "=r"(cur) : "l"(&g_bar) : "memory");
    } while ((int)(cur - target) < 0);
  }
  __syncthreads();
}
__device__ __forceinline__ float sigf(float x)     { return 1.f/(1.f+__expf(-x)); }
__device__ __forceinline__ float tanhfast(float x) { return 1.f - 2.f/(1.f+__expf(2.f*x)); }

// ---------------- prep kernels ----------------
extern "C" __global__ void conv_x_kernel(const float* x) {
  for (size_t idx = (size_t)blockIdx.x*blockDim.x + threadIdx.x;
       idx < (size_t)NB*NT*DIN; idx += (size_t)gridDim.x*blockDim.x) {
    int d = (int)(idx & (DIN-1));
    int t = (int)((idx >> 9) & (NT-1));
    int b = (int)(idx >> 18);
    g_Xh[((size_t)(t*NB + b))*DIN + d] = __float2half_rn(x[idx]);
  }
}

// in: f32 [R][C]  ->  out: f16 [C][R]
extern "C" __global__ void transpose_kernel(const float* in, __half* out, int R, int C) {
  __shared__ float tile[32][33];
  int cx = blockIdx.x*32, ry = blockIdx.y*32;
  #pragma unroll
  for (int j = 0; j < 4; ++j) {
    int r = ry + threadIdx.y + j*8;
    tile[threadIdx.y + j*8][threadIdx.x] = in[(size_t)r*C + cx + threadIdx.x];
  }
  __syncthreads();
  #pragma unroll
  for (int j = 0; j < 4; ++j) {
    int ro = cx + threadIdx.y + j*8;          // output row = input col
    out[(size_t)ro*R + ry + threadIdx.x] = __float2half_rn(tile[threadIdx.x][threadIdx.y + j*8]);
  }
}

// ---------------- prepass GEMM: C[M,4096] = A[M,K] @ WT^T + bias ----------------
// A f16 [M][K], WT f16 [4096][K], C f32. Tile 128m x 64n, k-chunk 64, double buffered.
#define GA_PITCH 144    // bytes per A row in smem (72 halves)
#define GB_PITCH 144
#define GAB (128*GA_PITCH)   // 18432
#define GBB (64*GB_PITCH)    // 9216
#define GSMEM (2*GAB + 2*GBB) // 55296

extern "C" __global__ void __launch_bounds__(NTHR, 2)
gemm_kernel(const __half* A, const __half* WT, const float* bias, float* C, int K) {
  extern __shared__ char sm[];
  char* As = sm;
  char* Bs = sm + 2*GAB;
  const int tid = threadIdx.x, lane = tid&31, wid = tid>>5;
  const int wm = wid>>1, wn = wid&1;
  const int r = lane>>2, c2 = lane&3;
  const int bm = blockIdx.x, bn = blockIdx.y;
  const int NC = K >> 6;

  float acc[2][4][4];
  #pragma unroll
  for (int nt = 0; nt < 4; ++nt) {
    float2 bv = *(const float2*)(bias + bn*64 + wn*32 + nt*8 + 2*c2);
    #pragma unroll
    for (int mt = 0; mt < 2; ++mt) {
      acc[mt][nt][0]=bv.x; acc[mt][nt][1]=bv.y; acc[mt][nt][2]=bv.x; acc[mt][nt][3]=bv.y;
    }
  }

#define GSTAGE(CH, BUF) do {                                               \
    unsigned da = sptr(As) + (BUF)*GAB;                                    \
    _Pragma("unroll")                                                      \
    for (int j = 0; j < 4; ++j) {                                          \
      int idx = tid + j*NTHR, row = idx>>3, seg = idx&7;                   \
      cp16(da + row*GA_PITCH + seg*16,                                     \
           A + (size_t)(bm*128+row)*K + (CH)*64 + seg*8);                  \
    }                                                                      \
    unsigned db = sptr(Bs) + (BUF)*GBB;                                    \
    _Pragma("unroll")                                                      \
    for (int j = 0; j < 2; ++j) {                                          \
      int idx = tid + j*NTHR, row = idx>>3, seg = idx&7;                   \
      cp16(db + row*GB_PITCH + seg*16,                                     \
           WT + (size_t)(bn*64+row)*K + (CH)*64 + seg*8);                  \
    }                                                                      \
    cpcommit();                                                            \
  } while(0)

  GSTAGE(0, 0);
  #pragma unroll 1
  for (int ch = 0; ch < NC; ++ch) {
    if (ch+1 < NC) { GSTAGE(ch+1, (ch+1)&1); cpwait1(); } else cpwait0();
    __syncthreads();
    unsigned ab = sptr(As) + (ch&1)*GAB;
    unsigned bb = sptr(Bs) + (ch&1)*GBB;
    const int sub = lane>>3, rsel = lane&7;
    #pragma unroll
    for (int s = 0; s < 4; ++s) {
      unsigned av[2][4];
      #pragma unroll
      for (int mt = 0; mt < 2; ++mt) {
        int row = wm*32 + mt*16 + (sub&1)*8 + rsel;
        ldsm4(av[mt], ab + row*GA_PITCH + s*32 + (sub>>1)*16);
      }
      #pragma unroll
      for (int nt = 0; nt < 4; ++nt) {
        unsigned brow = bb + (wn*32 + nt*8 + r)*GB_PITCH + s*32 + c2*4;
        unsigned bv[2];
        bv[0] = *(const unsigned*)__cvta_shared_to_generic(brow);
        bv[1] = *(const unsigned*)__cvta_shared_to_generic(brow + 16);
        #pragma unroll
        for (int mt = 0; mt < 2; ++mt) hmma(acc[mt][nt], av[mt], bv);
      }
    }
    __syncthreads();
  }
#undef GSTAGE

  #pragma unroll
  for (int mt = 0; mt < 2; ++mt) {
    int row = bm*128 + wm*32 + mt*16 + r;
    #pragma unroll
    for (int nt = 0; nt < 4; ++nt) {
      int col = bn*64 + wn*32 + nt*8 + 2*c2;
      float* p = C + (size_t)row*4096 + col;
      *(float2*)p              = make_float2(acc[mt][nt][0], acc[mt][nt][1]);
      *(float2*)(p + 8*4096)   = make_float2(acc[mt][nt][2], acc[mt][nt][3]);
    }
  }
}

// ---------------- recurrent kernel ----------------
// Per CTA: 8 h-cols (32 gate cols). 8 warps = 2 m-halves x 4 k-quarters (k-split).
// A (=h_t, 64x1024 f16) staged warp-privately; U fragments preloaded in registers.
#define AWP 528                 // bytes per A row in smem (264 halves)
#define AWB (32*AWP)            // 16896 per warp
#define UPH 1032                // U bounce pitch (halves)
#define RPACC_OFF 135168
#define RPACC_PITCH 34
#define RCS_OFF 169984
#define RSMEM 172032

template<int LAYER>
__global__ void __launch_bounds__(NTHR, 1)
rec_kernel(const float* h0, const float* c0, const __half* UT,
           float* out, int out_size)
{
  extern __shared__ char sm[];
  float* pacc = (float*)(sm + RPACC_OFF);
  float* cs   = (float*)(sm + RCS_OFF);
  const int tid = threadIdx.x, cta = blockIdx.x;
  const int lane = tid&31, wid = tid>>5;
  const int wm = wid&1, ks = wid>>1;
  const int r = lane>>2, c2 = lane&3;
  const int sub = lane>>3, rsel = lane&7;

  // ---- init: c, h0 ----
  #pragma unroll
  for (int e0 = 0; e0 < 2; ++e0) {
    int item = tid + e0*NTHR;
    int b = item>>3, hc = item&7, col = cta*8 + hc;
    cs[item] = c0[b*HID + col];
    g_H[0][b*HID + col] = __float2half_rn(h0[b*HID + col]);
  }

  // ---- U bounce into smem, lift fragments into registers ----
  {
    __half* ub = (__half*)sm;
    unsigned du = sptr(ub);
    #pragma unroll
    for (int j = 0; j < 16; ++j) {
      int idx = tid + j*NTHR;       // 4096 = 32 rows x 128 segs
      int row = idx >> 7, seg = idx & 127;
      int gcol = (row>>3)*HID + cta*8 + (row&7);
      cp16(du + row*(UPH*2) + seg*16, UT + (size_t)gcol*HID + seg*8);
    }
    cpcommit(); cpwait0();
  }
  __syncthreads();

  unsigned bfr[16][4][2];
  {
    const __half* ub = (const __half*)sm;
    #pragma unroll
    for (int s = 0; s < 16; ++s) {
      int k = ks*256 + s*16 + 2*c2;
      #pragma unroll
      for (int nt = 0; nt < 4; ++nt) {
        const __half* p = ub + (nt*8 + r)*UPH + k;
        bfr[s][nt][0] = *(const unsigned*)(p);
        bfr[s][nt][1] = *(const unsigned*)(p + 8);
      }
    }
  }
  __syncthreads();   // done with bounce; A staging may overwrite
  gridbar();         // g_H[0] fully written by all CTAs

  char* wb = sm + wid*AWB;
  unsigned wbs = sptr(wb);

  for (int t = 0; t < NT; ++t) {
    const __half* hs = g_H[t&1];

    // warp-private A staging: rows [wm*32, +32), k [ks*256, +256)
    #pragma unroll
    for (int i = 0; i < 32; ++i) {
      cp16(wbs + i*AWP + lane*16,
           hs + (size_t)(wm*32 + i)*HID + ks*256 + lane*8);
    }
    cpcommit(); cpwait0();
    __syncwarp();

    float acc[2][4][4];
    #pragma unroll
    for (int mt = 0; mt < 2; ++mt)
      #pragma unroll
      for (int nt = 0; nt < 4; ++nt)
        acc[mt][nt][0]=acc[mt][nt][1]=acc[mt][nt][2]=acc[mt][nt][3]=0.f;

    #pragma unroll
    for (int s = 0; s < 16; ++s) {
      unsigned av[2][4];
      #pragma unroll
      for (int mt = 0; mt < 2; ++mt) {
        int row = mt*16 + (sub&1)*8 + rsel;
        ldsm4(av[mt], wbs + row*AWP + s*32 + (sub>>1)*16);
      }
      #pragma unroll
      for (int nt = 0; nt < 4; ++nt)
        #pragma unroll
        for (int mt = 0; mt < 2; ++mt)
          hmma(acc[mt][nt], av[mt], bfr[s][nt]);
    }

    // write k-split partials
    #pragma unroll
    for (int mt = 0; mt < 2; ++mt) {
      int row = wm*32 + mt*16 + r;
      #pragma unroll
      for (int nt = 0; nt < 4; ++nt) {
        int col = nt*8 + 2*c2;
        float* p = pacc + (ks*64 + row)*RPACC_PITCH + col;
        *(float2*)p                      = make_float2(acc[mt][nt][0], acc[mt][nt][1]);
        *(float2*)(p + 8*RPACC_PITCH)    = make_float2(acc[mt][nt][2], acc[mt][nt][3]);
      }
    }
    __syncthreads();

    // reduce + gate base + LSTM cell
    #pragma unroll
    for (int e0 = 0; e0 < 2; ++e0) {
      int item = tid + e0*NTHR;
      int b = item>>3, hc = item&7;
      float gi=0.f, gf=0.f, gg=0.f, go=0.f;
      #pragma unroll
      for (int q = 0; q < 4; ++q) {
        const float* p = pacc + (q*64 + b)*RPACC_PITCH;
        gi += p[hc]; gf += p[8+hc]; gg += p[16+hc]; go += p[24+hc];
      }
      const float* gb = g_GB + ((size_t)(t*NB + b))*(4*HID) + cta*8 + hc;
      gi += gb[0]; gf += gb[HID]; gg += gb[2*HID]; go += gb[3*HID];
      float cprev = cs[item];
      float cn = sigf(gf)*cprev + sigf(gi)*tanhfast(gg);
      float hn = sigf(go)*tanhfast(cn);
      cs[item] = cn;
      int col = cta*8 + hc;
      g_H[(t+1)&1][b*HID + col] = __float2half_rn(hn);
      if (LAYER == 0) {
        g_X1[((size_t)(t*NB + b))*HID + col] = __float2half_rn(hn);
      } else {
        out[((size_t)b*NT + t)*HID + col] = hn;
        if (t == NT-1 && out_size >= NB*NT*HID + 2*NB*HID) {
          out[(size_t)NB*NT*HID + b*HID + col]          = hn;
          out[(size_t)NB*NT*HID + NB*HID + b*HID + col] = cn;
        }
      }
    }
    gridbar();
  }
}

// ---------------- host launch ----------------
extern "C" void kernel_launch(void* const* d_in, const int* in_sizes, int n_in,
                              void* d_out, int out_size) {
  const float* x  = (const float*)d_in[0];
  const float* h0 = (const float*)d_in[1];
  const float* c0 = (const float*)d_in[2];
  const float* W0 = (const float*)d_in[3];
  const float* U0 = (const float*)d_in[4];
  const float* b0 = (const float*)d_in[5];
  const float* W1 = (const float*)d_in[6];
  const float* U1 = (const float*)d_in[7];
  const float* b1 = (const float*)d_in[8];
  float* out = (float*)d_out;

  static int once = 0;
  if (!once) {
    cudaFuncSetAttribute(gemm_kernel, cudaFuncAttributeMaxDynamicSharedMemorySize, GSMEM);
    cudaFuncSetAttribute(rec_kernel<0>, cudaFuncAttributeMaxDynamicSharedMemorySize, RSMEM);
    cudaFuncSetAttribute(rec_kernel<1>, cudaFuncAttributeMaxDynamicSharedMemorySize, RSMEM);
    once = 1;
  }

  __half *pW0T, *pW1T, *pU0T, *pU1T, *pXh, *pX1;
  float* pGB;
  cudaGetSymbolAddress((void**)&pW0T, g_W0T);
  cudaGetSymbolAddress((void**)&pW1T, g_W1T);
  cudaGetSymbolAddress((void**)&pU0T, g_U0T);
  cudaGetSymbolAddress((void**)&pU1T, g_U1T);
  cudaGetSymbolAddress((void**)&pXh,  g_Xh);
  cudaGetSymbolAddress((void**)&pX1,  g_X1);
  cudaGetSymbolAddress((void**)&pGB,  g_GB);

  conv_x_kernel<<<512, 256>>>(x);
  dim3 tb(32, 8);
  transpose_kernel<<<dim3(4*HID/32, DIN/32), tb>>>(W0, pW0T, DIN, 4*HID);
  transpose_kernel<<<dim3(4*HID/32, HID/32), tb>>>(W1, pW1T, HID, 4*HID);
  transpose_kernel<<<dim3(4*HID/32, HID/32), tb>>>(U0, pU0T, HID, 4*HID);
  transpose_kernel<<<dim3(4*HID/32, HID/32), tb>>>(U1, pU1T, HID, 4*HID);

  gemm_kernel<<<dim3(NT*NB/128, 4*HID/64), NTHR, GSMEM>>>(pXh, pW0T, b0, pGB, DIN);
  rec_kernel<0><<<NCTA, NTHR, RSMEM>>>(h0, c0, pU0T, out, out_size);
  gemm_kernel<<<dim3(NT*NB/128, 4*HID/64), NTHR, GSMEM>>>(pX1, pW1T, b1, pGB, HID);
  rec_kernel<1><<<NCTA, NTHR, RSMEM>>>(h0 + NB*HID, c0 + NB*HID, pU1T, out, out_size);
}